// round 1
// baseline (speedup 1.0000x reference)
#include <cuda_runtime.h>
#include <math.h>
#include <float.h>

// ---------------- problem constants ----------------
#define F_DIM 2048
#define H_DIM 256
#define C_DIM 64
#define K_DIM 16
#define TOPK  10
#define N_MAX 65536
#define EPS   1e-6f

// ---------------- device scratch (no allocs allowed) ----------------
__device__ float g_wdiff[F_DIM];
__device__ float g_scores[N_MAX];
__device__ int   g_topidx[TOPK];
__device__ float g_fp[(TOPK + C_DIM) * H_DIM];   // rows 0..9 = f, rows 10..73 = p

// ---------------- K0: w_diff = W3[:,1] - W3[:,0] ----------------
__global__ void k0_wdiff(const float* __restrict__ W3) {
    int k = blockIdx.x * blockDim.x + threadIdx.x;
    if (k < F_DIM) g_wdiff[k] = W3[2 * k + 1] - W3[2 * k + 0];
}

// ---------------- K1: scores[row] = x[row] . w_diff + (b3[1]-b3[0]) ----------------
// 8 warps/block, one row per warp, float4 coalesced loads.
__global__ void __launch_bounds__(256) k1_scores(const float* __restrict__ x,
                                                 const float* __restrict__ b3,
                                                 int N) {
    __shared__ float ws[F_DIM];
    int tid = threadIdx.x;
    // stage w_diff into smem (float4)
    float4* ws4 = reinterpret_cast<float4*>(ws);
    const float4* wd4 = reinterpret_cast<const float4*>(g_wdiff);
    ws4[tid]       = wd4[tid];
    ws4[tid + 256] = wd4[tid + 256];
    __syncthreads();

    int warp = tid >> 5;
    int lane = tid & 31;
    int row  = blockIdx.x * 8 + warp;
    if (row >= N) return;

    const float4* xr = reinterpret_cast<const float4*>(x + (size_t)row * F_DIM);
    float acc = 0.f;
#pragma unroll
    for (int it = 0; it < 16; it++) {
        float4 xv = xr[lane + it * 32];
        float4 wv = ws4[lane + it * 32];
        acc = fmaf(xv.x, wv.x, acc);
        acc = fmaf(xv.y, wv.y, acc);
        acc = fmaf(xv.z, wv.z, acc);
        acc = fmaf(xv.w, wv.w, acc);
    }
#pragma unroll
    for (int o = 16; o; o >>= 1) acc += __shfl_down_sync(0xffffffffu, acc, o);
    if (lane == 0) g_scores[row] = acc + (b3[1] - b3[0]);
}

// ---------------- K2: top-10 selection (single block) ----------------
__device__ __forceinline__ bool better(float av, int ai, float bv, int bi) {
    return (av > bv) || (av == bv && ai < bi);   // ties: lowest index first
}

__global__ void __launch_bounds__(512) k2_topk(int N) {
    __shared__ float sv[512 * TOPK];
    __shared__ int   si[512 * TOPK];
    int tid = threadIdx.x;

    float lv[TOPK];
    int   li[TOPK];
#pragma unroll
    for (int j = 0; j < TOPK; j++) { lv[j] = -FLT_MAX; li[j] = 0x7fffffff; }

    for (int i = tid; i < N; i += 512) {
        float v = g_scores[i];
        if (better(v, i, lv[TOPK - 1], li[TOPK - 1])) {
            int j = TOPK - 1;
            while (j > 0 && better(v, i, lv[j - 1], li[j - 1])) {
                lv[j] = lv[j - 1]; li[j] = li[j - 1]; j--;
            }
            lv[j] = v; li[j] = i;
        }
    }
#pragma unroll
    for (int j = 0; j < TOPK; j++) { sv[tid * TOPK + j] = lv[j]; si[tid * TOPK + j] = li[j]; }

    for (int s = 256; s > 0; s >>= 1) {
        __syncthreads();
        if (tid < s) {
            float mv[TOPK]; int mi[TOPK];
            int a = 0, b = 0;
#pragma unroll
            for (int j = 0; j < TOPK; j++) {
                float av = sv[tid * TOPK + a];       int ai = si[tid * TOPK + a];
                float bvv = sv[(tid + s) * TOPK + b]; int bi = si[(tid + s) * TOPK + b];
                if (better(av, ai, bvv, bi)) { mv[j] = av; mi[j] = ai; a++; }
                else                         { mv[j] = bvv; mi[j] = bi; b++; }
            }
#pragma unroll
            for (int j = 0; j < TOPK; j++) { sv[tid * TOPK + j] = mv[j]; si[tid * TOPK + j] = mi[j]; }
        }
    }
    __syncthreads();
    if (tid < TOPK) g_topidx[tid] = si[tid];
}

// ---------------- K3: f = m_features@W2+b2 ; p = prototype@W2+b2 ----------------
// 74 blocks, one output row each; 256 threads = one output column each.
__global__ void __launch_bounds__(256) k3_embed(const float* __restrict__ x,
                                                const float* __restrict__ proto,
                                                const float* __restrict__ W2,
                                                const float* __restrict__ b2) {
    __shared__ float xs[F_DIM];
    int r = blockIdx.x;
    int t = threadIdx.x;

    const float* src = (r < TOPK) ? (x + (size_t)g_topidx[r] * F_DIM)
                                  : (proto + (size_t)(r - TOPK) * F_DIM);
    float4* xs4 = reinterpret_cast<float4*>(xs);
    const float4* s4 = reinterpret_cast<const float4*>(src);
    xs4[t]       = s4[t];
    xs4[t + 256] = s4[t + 256];
    __syncthreads();

    float a0 = 0.f, a1 = 0.f, a2 = 0.f, a3 = 0.f;
#pragma unroll 4
    for (int k = 0; k < F_DIM; k += 4) {
        a0 = fmaf(xs[k + 0], W2[(k + 0) * H_DIM + t], a0);
        a1 = fmaf(xs[k + 1], W2[(k + 1) * H_DIM + t], a1);
        a2 = fmaf(xs[k + 2], W2[(k + 2) * H_DIM + t], a2);
        a3 = fmaf(xs[k + 3], W2[(k + 3) * H_DIM + t], a3);
    }
    g_fp[r * H_DIM + t] = b2[t] + ((a0 + a1) + (a2 + a3));
}

// ---------------- K4: similarity + normalize + mean + rho/relu/classifier ----------------
__global__ void __launch_bounds__(640) k4_head(const float* __restrict__ Wrho,
                                               const float* __restrict__ brho,
                                               const float* __restrict__ Wc,
                                               const float* __restrict__ bc,
                                               float* __restrict__ out,
                                               int out_size) {
    __shared__ float sim[TOPK][C_DIM];
    __shared__ float rowmax[TOPK];
    __shared__ float coding[C_DIM];
    __shared__ float hidden[K_DIM];
    __shared__ float logits[2];
    int t = threadIdx.x;

    if (t < TOPK * C_DIM) {
        int r = t / C_DIM, c = t % C_DIM;
        const float* f = g_fp + r * H_DIM;
        const float* p = g_fp + (TOPK + c) * H_DIM;
        float s = 0.f;
#pragma unroll 8
        for (int h = 0; h < H_DIM; h++) {
            float d = f[h] - p[h] + EPS;
            s = fmaf(d, d, s);
        }
        sim[r][c] = sqrtf(s);
    }
    __syncthreads();
    if (t < TOPK) {
        float m = sim[t][0];
#pragma unroll
        for (int c = 1; c < C_DIM; c++) m = fmaxf(m, sim[t][c]);
        rowmax[t] = m;
    }
    __syncthreads();
    if (t < C_DIM) {
        float s = 0.f;
#pragma unroll
        for (int r = 0; r < TOPK; r++) s += sim[r][t] / rowmax[r];
        coding[t] = s / (float)TOPK;
    }
    __syncthreads();
    if (t < K_DIM) {
        float h = brho[t];
#pragma unroll
        for (int c = 0; c < C_DIM; c++) h = fmaf(coding[c], Wrho[c * K_DIM + t], h);
        hidden[t] = fmaxf(h, 0.f);
    }
    __syncthreads();
    if (t < 2) {
        float l = bc[t];
#pragma unroll
        for (int k = 0; k < K_DIM; k++) l = fmaf(hidden[k], Wc[k * 2 + t], l);
        logits[t] = l;
    }
    __syncthreads();
    if (t == 0) {
        float l0 = logits[0], l1 = logits[1];
        float m  = fmaxf(l0, l1);
        float e0 = expf(l0 - m), e1 = expf(l1 - m);
        float inv = 1.f / (e0 + e1);
        float p0 = e0 * inv, p1 = e1 * inv;

        float vals[5 + C_DIM];
        vals[0] = l0; vals[1] = l1;
        vals[2] = p0; vals[3] = p1;
        vals[4] = (p1 > p0) ? 1.f : 0.f;   // argmax, ties -> 0
#pragma unroll
        for (int c = 0; c < C_DIM; c++) vals[5 + c] = coding[c];

        int n = out_size < (5 + C_DIM) ? out_size : (5 + C_DIM);
        for (int i = 0; i < n; i++) out[i] = vals[i];
    }
}

// ---------------- host launcher ----------------
extern "C" void kernel_launch(void* const* d_in, const int* in_sizes, int n_in,
                              void* d_out, int out_size) {
    const float* x     = (const float*)d_in[0];
    const float* proto = (const float*)d_in[1];
    const float* W3    = (const float*)d_in[2];
    const float* b3    = (const float*)d_in[3];
    const float* W2    = (const float*)d_in[4];
    const float* b2    = (const float*)d_in[5];
    const float* Wrho  = (const float*)d_in[6];
    const float* brho  = (const float*)d_in[7];
    const float* Wc    = (const float*)d_in[8];
    const float* bc    = (const float*)d_in[9];
    float* out = (float*)d_out;

    int N = in_sizes[0] / F_DIM;
    if (N > N_MAX) N = N_MAX;

    k0_wdiff<<<(F_DIM + 255) / 256, 256>>>(W3);
    k1_scores<<<(N + 7) / 8, 256>>>(x, b3, N);
    k2_topk<<<1, 512>>>(N);
    k3_embed<<<TOPK + C_DIM, 256>>>(x, proto, W2, b2);
    k4_head<<<1, 640>>>(Wrho, brho, Wc, bc, out, out_size);
}

// round 2
// speedup vs baseline: 1.2330x; 1.2330x over previous
#include <cuda_runtime.h>
#include <math.h>
#include <float.h>

// ---------------- problem constants ----------------
#define F_DIM 2048
#define H_DIM 256
#define C_DIM 64
#define K_DIM 16
#define TOPK  10
#define N_MAX 65536
#define EPS   1e-6f
#define R_TOT (TOPK + C_DIM)     // 74 embedding rows
#define KCH   8                  // K-chunks for k3
#define KCSZ  (F_DIM / KCH)      // 256
#define RG    8                  // rows per k3 block
#define NRG   ((R_TOT + RG - 1) / RG)  // 10

// ---------------- device scratch ----------------
__device__ float g_wdiff[F_DIM];
__device__ float g_scores[N_MAX];
__device__ int   g_topidx[TOPK];
__device__ float g_part[R_TOT * KCH * H_DIM];    // partial embeddings
__device__ float g_fp[R_TOT * H_DIM];            // rows 0..9 = f, 10..73 = p

// ---------------- K0: w_diff = W3[:,1] - W3[:,0] ----------------
__global__ void k0_wdiff(const float* __restrict__ W3) {
    int k = blockIdx.x * blockDim.x + threadIdx.x;
    if (k < F_DIM) g_wdiff[k] = W3[2 * k + 1] - W3[2 * k + 0];
}

// ---------------- K1: scores = x . w_diff + (b3[1]-b3[0]) ----------------
// 512 threads = 16 warps = 16 rows per block; float4 streaming loads.
__global__ void __launch_bounds__(512) k1_scores(const float* __restrict__ x,
                                                 const float* __restrict__ b3,
                                                 int N) {
    __shared__ float ws[F_DIM];
    int tid = threadIdx.x;
    float4* ws4 = reinterpret_cast<float4*>(ws);
    const float4* wd4 = reinterpret_cast<const float4*>(g_wdiff);
    ws4[tid] = wd4[tid];
    __syncthreads();

    int warp = tid >> 5;
    int lane = tid & 31;
    int row  = blockIdx.x * 16 + warp;
    if (row >= N) return;

    const float4* xr = reinterpret_cast<const float4*>(x + (size_t)row * F_DIM);
    float acc = 0.f;
#pragma unroll
    for (int it = 0; it < 16; it++) {
        float4 xv = xr[lane + it * 32];
        float4 wv = ws4[lane + it * 32];
        acc = fmaf(xv.x, wv.x, acc);
        acc = fmaf(xv.y, wv.y, acc);
        acc = fmaf(xv.z, wv.z, acc);
        acc = fmaf(xv.w, wv.w, acc);
    }
#pragma unroll
    for (int o = 16; o; o >>= 1) acc += __shfl_down_sync(0xffffffffu, acc, o);
    if (lane == 0) g_scores[row] = acc + (b3[1] - b3[0]);
}

// ---------------- K2: top-10 selection (single block, batched loads) ----------------
__device__ __forceinline__ bool better(float av, int ai, float bv, int bi) {
    return (av > bv) || (av == bv && ai < bi);   // ties: lowest index first
}

__global__ void __launch_bounds__(512) k2_topk(int N) {
    __shared__ float sv[512 * TOPK];
    __shared__ int   si[512 * TOPK];
    int tid = threadIdx.x;

    float lv[TOPK];
    int   li[TOPK];
#pragma unroll
    for (int j = 0; j < TOPK; j++) { lv[j] = -FLT_MAX; li[j] = 0x7fffffff; }

    const float4* s4 = reinterpret_cast<const float4*>(g_scores);
    int nv4 = N >> 2;                          // N is a multiple of 4 here
    for (int j0 = tid; j0 < nv4; j0 += 512 * 8) {
        float4 v[8];
        int    vi[8];
#pragma unroll
        for (int u = 0; u < 8; u++) {          // batch 8 independent loads
            int j = j0 + 512 * u;
            vi[u] = j;
            if (j < nv4) v[u] = s4[j];
            else { v[u].x = v[u].y = v[u].z = v[u].w = -FLT_MAX; }
        }
#pragma unroll
        for (int u = 0; u < 8; u++) {
            float e[4] = { v[u].x, v[u].y, v[u].z, v[u].w };
#pragma unroll
            for (int q = 0; q < 4; q++) {
                int idx = vi[u] * 4 + q;
                if (better(e[q], idx, lv[TOPK - 1], li[TOPK - 1])) {
                    int j = TOPK - 1;
                    while (j > 0 && better(e[q], idx, lv[j - 1], li[j - 1])) {
                        lv[j] = lv[j - 1]; li[j] = li[j - 1]; j--;
                    }
                    lv[j] = e[q]; li[j] = idx;
                }
            }
        }
    }
#pragma unroll
    for (int j = 0; j < TOPK; j++) { sv[tid * TOPK + j] = lv[j]; si[tid * TOPK + j] = li[j]; }

    for (int s = 256; s > 0; s >>= 1) {
        __syncthreads();
        if (tid < s) {
            float mv[TOPK]; int mi[TOPK];
            int a = 0, b = 0;
#pragma unroll
            for (int j = 0; j < TOPK; j++) {
                float av = sv[tid * TOPK + a];        int ai = si[tid * TOPK + a];
                float bvv = sv[(tid + s) * TOPK + b]; int bi = si[(tid + s) * TOPK + b];
                if (better(av, ai, bvv, bi)) { mv[j] = av;  mi[j] = ai; a++; }
                else                         { mv[j] = bvv; mi[j] = bi; b++; }
            }
#pragma unroll
            for (int j = 0; j < TOPK; j++) { sv[tid * TOPK + j] = mv[j]; si[tid * TOPK + j] = mi[j]; }
        }
    }
    __syncthreads();
    if (tid < TOPK) g_topidx[tid] = si[tid];
}

// ---------------- K3a: partial embeddings ----------------
// grid = (NRG row-groups, KCH k-chunks). Block: 256 threads = one H column each.
// Each block stages RG rows' x-chunk in smem; each W2 load feeds RG FMAs.
__global__ void __launch_bounds__(256) k3a_partial(const float* __restrict__ x,
                                                   const float* __restrict__ proto,
                                                   const float* __restrict__ W2) {
    __shared__ float xs[RG][KCSZ];
    int t  = threadIdx.x;
    int rg = blockIdx.x;
    int kc = blockIdx.y;
    int kbase = kc * KCSZ;

#pragma unroll
    for (int i = 0; i < RG; i++) {
        int r = rg * RG + i;
        float v = 0.f;
        if (r < R_TOT) {
            const float* src = (r < TOPK) ? (x + (size_t)g_topidx[r] * F_DIM)
                                          : (proto + (size_t)(r - TOPK) * F_DIM);
            v = src[kbase + t];
        }
        xs[i][t] = v;
    }
    __syncthreads();

    float acc[RG];
#pragma unroll
    for (int i = 0; i < RG; i++) acc[i] = 0.f;

#pragma unroll 4
    for (int k = 0; k < KCSZ; k++) {
        float w = W2[(size_t)(kbase + k) * H_DIM + t];
#pragma unroll
        for (int i = 0; i < RG; i++) acc[i] = fmaf(xs[i][k], w, acc[i]);
    }

#pragma unroll
    for (int i = 0; i < RG; i++) {
        int r = rg * RG + i;
        if (r < R_TOT) g_part[((size_t)r * KCH + kc) * H_DIM + t] = acc[i];
    }
}

// ---------------- K3b: reduce partials + bias ----------------
__global__ void __launch_bounds__(256) k3b_reduce(const float* __restrict__ b2) {
    int r = blockIdx.x;
    int t = threadIdx.x;
    float s = b2[t];
#pragma unroll
    for (int c = 0; c < KCH; c++) s += g_part[((size_t)r * KCH + c) * H_DIM + t];
    g_fp[r * H_DIM + t] = s;
}

// ---------------- K4: similarity + normalize + mean + head ----------------
__global__ void __launch_bounds__(640) k4_head(const float* __restrict__ Wrho,
                                               const float* __restrict__ brho,
                                               const float* __restrict__ Wc,
                                               const float* __restrict__ bc,
                                               float* __restrict__ out,
                                               int out_size) {
    __shared__ float fs[TOPK][H_DIM];
    __shared__ float sim[TOPK][C_DIM];
    __shared__ float rowmax[TOPK];
    __shared__ float coding[C_DIM];
    __shared__ float hidden[K_DIM];
    __shared__ float logits[2];
    int t = threadIdx.x;

    // stage f rows (10 x 256) into smem
    for (int i = t; i < TOPK * H_DIM; i += 640) fs[i / H_DIM][i % H_DIM] = g_fp[i];
    __syncthreads();

    if (t < TOPK * C_DIM) {
        int r = t / C_DIM, c = t % C_DIM;
        const float* p = g_fp + (TOPK + c) * H_DIM;
        float s0 = 0.f, s1 = 0.f;
#pragma unroll 4
        for (int h = 0; h < H_DIM; h += 2) {
            float d0 = fs[r][h]     - __ldg(p + h)     + EPS;
            float d1 = fs[r][h + 1] - __ldg(p + h + 1) + EPS;
            s0 = fmaf(d0, d0, s0);
            s1 = fmaf(d1, d1, s1);
        }
        sim[r][c] = sqrtf(s0 + s1);
    }
    __syncthreads();
    if (t < TOPK) {
        float m = sim[t][0];
#pragma unroll
        for (int c = 1; c < C_DIM; c++) m = fmaxf(m, sim[t][c]);
        rowmax[t] = m;
    }
    __syncthreads();
    if (t < C_DIM) {
        float s = 0.f;
#pragma unroll
        for (int r = 0; r < TOPK; r++) s += sim[r][t] / rowmax[r];
        coding[t] = s / (float)TOPK;
    }
    __syncthreads();
    if (t < K_DIM) {
        float h = brho[t];
#pragma unroll
        for (int c = 0; c < C_DIM; c++) h = fmaf(coding[c], Wrho[c * K_DIM + t], h);
        hidden[t] = fmaxf(h, 0.f);
    }
    __syncthreads();
    if (t < 2) {
        float l = bc[t];
#pragma unroll
        for (int k = 0; k < K_DIM; k++) l = fmaf(hidden[k], Wc[k * 2 + t], l);
        logits[t] = l;
    }
    __syncthreads();
    if (t == 0) {
        float l0 = logits[0], l1 = logits[1];
        float m  = fmaxf(l0, l1);
        float e0 = expf(l0 - m), e1 = expf(l1 - m);
        float inv = 1.f / (e0 + e1);
        float p0 = e0 * inv, p1 = e1 * inv;

        float vals[5 + C_DIM];
        vals[0] = l0; vals[1] = l1;
        vals[2] = p0; vals[3] = p1;
        vals[4] = (p1 > p0) ? 1.f : 0.f;
#pragma unroll
        for (int c = 0; c < C_DIM; c++) vals[5 + c] = coding[c];

        int n = out_size < (5 + C_DIM) ? out_size : (5 + C_DIM);
        for (int i = 0; i < n; i++) out[i] = vals[i];
    }
}

// ---------------- host launcher ----------------
extern "C" void kernel_launch(void* const* d_in, const int* in_sizes, int n_in,
                              void* d_out, int out_size) {
    const float* x     = (const float*)d_in[0];
    const float* proto = (const float*)d_in[1];
    const float* W3    = (const float*)d_in[2];
    const float* b3    = (const float*)d_in[3];
    const float* W2    = (const float*)d_in[4];
    const float* b2    = (const float*)d_in[5];
    const float* Wrho  = (const float*)d_in[6];
    const float* brho  = (const float*)d_in[7];
    const float* Wc    = (const float*)d_in[8];
    const float* bc    = (const float*)d_in[9];
    float* out = (float*)d_out;

    int N = in_sizes[0] / F_DIM;
    if (N > N_MAX) N = N_MAX;

    k0_wdiff<<<(F_DIM + 255) / 256, 256>>>(W3);
    k1_scores<<<(N + 15) / 16, 512>>>(x, b3, N);
    k2_topk<<<1, 512>>>(N);
    dim3 g3(NRG, KCH);
    k3a_partial<<<g3, 256>>>(x, proto, W2);
    k3b_reduce<<<R_TOT, 256>>>(b2);
    k4_head<<<1, 640>>>(Wrho, brho, Wc, bc, out, out_size);
}

// round 3
// speedup vs baseline: 1.9041x; 1.5443x over previous
#include <cuda_runtime.h>
#include <math.h>
#include <float.h>

// ---------------- problem constants ----------------
#define F_DIM 2048
#define H_DIM 256
#define C_DIM 64
#define K_DIM 16
#define TOPK  10
#define N_MAX 65536
#define EPS   1e-6f
#define R_TOT (TOPK + C_DIM)           // 74 embedding rows
#define KCH   16                       // K-chunks for k3
#define KCSZ  (F_DIM / KCH)            // 128
#define RG    8                        // rows per k3 block
#define NRG   ((R_TOT + RG - 1) / RG)  // 10
#define PADW  257                      // padded row width for k4 smem (conflict-free)

// ---------------- device scratch ----------------
__device__ float g_wdiff[F_DIM];
__device__ float g_scores[N_MAX];
__device__ int   g_topidx[TOPK];
__device__ float g_part[R_TOT * KCH * H_DIM];
__device__ float g_fp[R_TOT * H_DIM];   // rows 0..9 = f, 10..73 = p

// ---------------- K0: w_diff = W3[:,1] - W3[:,0] ----------------
__global__ void k0_wdiff(const float* __restrict__ W3) {
    int k = blockIdx.x * blockDim.x + threadIdx.x;
    if (k < F_DIM) g_wdiff[k] = W3[2 * k + 1] - W3[2 * k + 0];
}

// ---------------- K1: scores = x . w_diff + (b3[1]-b3[0]) ----------------
__global__ void __launch_bounds__(512) k1_scores(const float* __restrict__ x,
                                                 const float* __restrict__ b3,
                                                 int N) {
    __shared__ float ws[F_DIM];
    int tid = threadIdx.x;
    float4* ws4 = reinterpret_cast<float4*>(ws);
    const float4* wd4 = reinterpret_cast<const float4*>(g_wdiff);
    ws4[tid] = wd4[tid];
    __syncthreads();

    int warp = tid >> 5;
    int lane = tid & 31;
    int row  = blockIdx.x * 16 + warp;
    if (row >= N) return;

    const float4* xr = reinterpret_cast<const float4*>(x + (size_t)row * F_DIM);
    float acc = 0.f;
#pragma unroll
    for (int it = 0; it < 16; it++) {
        float4 xv = xr[lane + it * 32];
        float4 wv = ws4[lane + it * 32];
        acc = fmaf(xv.x, wv.x, acc);
        acc = fmaf(xv.y, wv.y, acc);
        acc = fmaf(xv.z, wv.z, acc);
        acc = fmaf(xv.w, wv.w, acc);
    }
#pragma unroll
    for (int o = 16; o; o >>= 1) acc += __shfl_down_sync(0xffffffffu, acc, o);
    if (lane == 0) g_scores[row] = acc + (b3[1] - b3[0]);
}

// ---------------- K2: top-10 selection ----------------
__device__ __forceinline__ bool better(float av, int ai, float bv, int bi) {
    return (av > bv) || (av == bv && ai < bi);
}

__global__ void __launch_bounds__(512) k2_topk(int N) {
    __shared__ float sv[512 * TOPK];
    __shared__ int   si[512 * TOPK];
    int tid = threadIdx.x;

    float lv[TOPK];
    int   li[TOPK];
#pragma unroll
    for (int j = 0; j < TOPK; j++) { lv[j] = -FLT_MAX; li[j] = 0x7fffffff; }

    const float4* s4 = reinterpret_cast<const float4*>(g_scores);
    int nv4 = N >> 2;
    for (int j0 = tid; j0 < nv4; j0 += 512 * 8) {
        float4 v[8];
        int    vi[8];
#pragma unroll
        for (int u = 0; u < 8; u++) {
            int j = j0 + 512 * u;
            vi[u] = j;
            if (j < nv4) v[u] = s4[j];
            else { v[u].x = v[u].y = v[u].z = v[u].w = -FLT_MAX; }
        }
#pragma unroll
        for (int u = 0; u < 8; u++) {
            float e[4] = { v[u].x, v[u].y, v[u].z, v[u].w };
#pragma unroll
            for (int q = 0; q < 4; q++) {
                int idx = vi[u] * 4 + q;
                if (better(e[q], idx, lv[TOPK - 1], li[TOPK - 1])) {
                    int j = TOPK - 1;
                    while (j > 0 && better(e[q], idx, lv[j - 1], li[j - 1])) {
                        lv[j] = lv[j - 1]; li[j] = li[j - 1]; j--;
                    }
                    lv[j] = e[q]; li[j] = idx;
                }
            }
        }
    }
#pragma unroll
    for (int j = 0; j < TOPK; j++) { sv[tid * TOPK + j] = lv[j]; si[tid * TOPK + j] = li[j]; }

    for (int s = 256; s > 0; s >>= 1) {
        __syncthreads();
        if (tid < s) {
            float mv[TOPK]; int mi[TOPK];
            int a = 0, b = 0;
#pragma unroll
            for (int j = 0; j < TOPK; j++) {
                float av = sv[tid * TOPK + a];        int ai = si[tid * TOPK + a];
                float bvv = sv[(tid + s) * TOPK + b]; int bi = si[(tid + s) * TOPK + b];
                if (better(av, ai, bvv, bi)) { mv[j] = av;  mi[j] = ai; a++; }
                else                         { mv[j] = bvv; mi[j] = bi; b++; }
            }
#pragma unroll
            for (int j = 0; j < TOPK; j++) { sv[tid * TOPK + j] = mv[j]; si[tid * TOPK + j] = mi[j]; }
        }
    }
    __syncthreads();
    if (tid < TOPK) g_topidx[tid] = si[tid];
}

// ---------------- K3a: partial embeddings, high-MLP ----------------
// grid (NRG, KCH) = (10, 16) = 160 blocks, 256 threads (one H column each).
// Manual 8-wide batching of W2 loads -> MLP=8 against DRAM/L2 latency.
__global__ void __launch_bounds__(256) k3a_partial(const float* __restrict__ x,
                                                   const float* __restrict__ proto,
                                                   const float* __restrict__ W2) {
    __shared__ float xs[RG][KCSZ];
    int t  = threadIdx.x;
    int rg = blockIdx.x;
    int kc = blockIdx.y;
    int kbase = kc * KCSZ;

    // stage RG rows' x-chunk: 256 threads cover 2 rows x 128 cols per step
    int rr = t >> 7;            // 0..1
    int cc = t & 127;           // 0..127
#pragma unroll
    for (int i = 0; i < RG; i += 2) {
        int r = rg * RG + i + rr;
        float v = 0.f;
        if (r < R_TOT) {
            const float* src = (r < TOPK) ? (x + (size_t)g_topidx[r] * F_DIM)
                                          : (proto + (size_t)(r - TOPK) * F_DIM);
            v = src[kbase + cc];
        }
        xs[i + rr][cc] = v;
    }
    __syncthreads();

    float acc[RG];
#pragma unroll
    for (int i = 0; i < RG; i++) acc[i] = 0.f;

    for (int k0 = 0; k0 < KCSZ; k0 += 8) {
        float w[8];
#pragma unroll
        for (int u = 0; u < 8; u++)       // 8 independent LDGs in flight
            w[u] = W2[(size_t)(kbase + k0 + u) * H_DIM + t];
#pragma unroll
        for (int u = 0; u < 8; u++)
#pragma unroll
            for (int i = 0; i < RG; i++)
                acc[i] = fmaf(xs[i][k0 + u], w[u], acc[i]);
    }

#pragma unroll
    for (int i = 0; i < RG; i++) {
        int r = rg * RG + i;
        if (r < R_TOT) g_part[((size_t)r * KCH + kc) * H_DIM + t] = acc[i];
    }
}

// ---------------- K3b: reduce partials + bias ----------------
__global__ void __launch_bounds__(256) k3b_reduce(const float* __restrict__ b2) {
    int r = blockIdx.x;
    int t = threadIdx.x;
    float s = b2[t];
#pragma unroll
    for (int c = 0; c < KCH; c++) s += g_part[((size_t)r * KCH + c) * H_DIM + t];
    g_fp[r * H_DIM + t] = s;
}

// ---------------- K4: similarity + normalize + mean + head ----------------
// All 74 rows staged into dynamic smem (padded width 257 -> conflict-free LDS).
// Prototype rows staged as q = p - EPS so d = f - q (2 FLOPs/element).
__global__ void __launch_bounds__(640) k4_head(const float* __restrict__ Wrho,
                                               const float* __restrict__ brho,
                                               const float* __restrict__ Wc,
                                               const float* __restrict__ bc,
                                               float* __restrict__ out,
                                               int out_size) {
    extern __shared__ float rows[];          // R_TOT * PADW floats
    __shared__ float sim[TOPK][C_DIM];
    __shared__ float rowmax[TOPK];
    __shared__ float coding[C_DIM];
    __shared__ float hidden[K_DIM];
    __shared__ float logits[2];
    int t = threadIdx.x;

    // stage g_fp -> smem with padding; subtract EPS on prototype rows
    for (int i = t; i < R_TOT * H_DIM; i += 640) {
        int r = i >> 8;          // /256
        int h = i & 255;
        float v = g_fp[i];
        if (r >= TOPK) v -= EPS;
        rows[r * PADW + h] = v;
    }
    __syncthreads();

    {
        int r = t / C_DIM;       // 0..9
        int c = t % C_DIM;       // 0..63 (t < 640 always valid)
        const float* f = rows + r * PADW;
        const float* q = rows + (TOPK + c) * PADW;
        float s0 = 0.f, s1 = 0.f, s2 = 0.f, s3 = 0.f;
#pragma unroll 8
        for (int h = 0; h < H_DIM; h += 4) {
            float d0 = f[h]     - q[h];
            float d1 = f[h + 1] - q[h + 1];
            float d2 = f[h + 2] - q[h + 2];
            float d3 = f[h + 3] - q[h + 3];
            s0 = fmaf(d0, d0, s0);
            s1 = fmaf(d1, d1, s1);
            s2 = fmaf(d2, d2, s2);
            s3 = fmaf(d3, d3, s3);
        }
        sim[r][c] = sqrtf((s0 + s1) + (s2 + s3));
    }
    __syncthreads();
    if (t < TOPK) {
        float m = sim[t][0];
#pragma unroll
        for (int c = 1; c < C_DIM; c++) m = fmaxf(m, sim[t][c]);
        rowmax[t] = m;
    }
    __syncthreads();
    if (t < C_DIM) {
        float s = 0.f;
#pragma unroll
        for (int r = 0; r < TOPK; r++) s += sim[r][t] / rowmax[r];
        coding[t] = s / (float)TOPK;
    }
    __syncthreads();
    if (t < K_DIM) {
        float h = brho[t];
#pragma unroll
        for (int c = 0; c < C_DIM; c++) h = fmaf(coding[c], Wrho[c * K_DIM + t], h);
        hidden[t] = fmaxf(h, 0.f);
    }
    __syncthreads();
    if (t < 2) {
        float l = bc[t];
#pragma unroll
        for (int k = 0; k < K_DIM; k++) l = fmaf(hidden[k], Wc[k * 2 + t], l);
        logits[t] = l;
    }
    __syncthreads();
    if (t == 0) {
        float l0 = logits[0], l1 = logits[1];
        float m  = fmaxf(l0, l1);
        float e0 = expf(l0 - m), e1 = expf(l1 - m);
        float inv = 1.f / (e0 + e1);
        float p0 = e0 * inv, p1 = e1 * inv;

        float vals[5 + C_DIM];
        vals[0] = l0; vals[1] = l1;
        vals[2] = p0; vals[3] = p1;
        vals[4] = (p1 > p0) ? 1.f : 0.f;
#pragma unroll
        for (int c = 0; c < C_DIM; c++) vals[5 + c] = coding[c];

        int n = out_size < (5 + C_DIM) ? out_size : (5 + C_DIM);
        for (int i = 0; i < n; i++) out[i] = vals[i];
    }
}

// ---------------- host launcher ----------------
extern "C" void kernel_launch(void* const* d_in, const int* in_sizes, int n_in,
                              void* d_out, int out_size) {
    const float* x     = (const float*)d_in[0];
    const float* proto = (const float*)d_in[1];
    const float* W3    = (const float*)d_in[2];
    const float* b3    = (const float*)d_in[3];
    const float* W2    = (const float*)d_in[4];
    const float* b2    = (const float*)d_in[5];
    const float* Wrho  = (const float*)d_in[6];
    const float* brho  = (const float*)d_in[7];
    const float* Wc    = (const float*)d_in[8];
    const float* bc    = (const float*)d_in[9];
    float* out = (float*)d_out;

    int N = in_sizes[0] / F_DIM;
    if (N > N_MAX) N = N_MAX;

    static int k4_smem_set = 0;
    int k4_smem = R_TOT * PADW * (int)sizeof(float);   // ~76 KB
    if (!k4_smem_set) {
        cudaFuncSetAttribute(k4_head, cudaFuncAttributeMaxDynamicSharedMemorySize, k4_smem);
        k4_smem_set = 1;
    }

    k0_wdiff<<<(F_DIM + 255) / 256, 256>>>(W3);
    k1_scores<<<(N + 15) / 16, 512>>>(x, b3, N);
    k2_topk<<<1, 512>>>(N);
    dim3 g3(NRG, KCH);
    k3a_partial<<<g3, 256>>>(x, proto, W2);
    k3b_reduce<<<R_TOT, 256>>>(b2);
    k4_head<<<1, 640, k4_smem>>>(Wrho, brho, Wc, bc, out, out_size);
}

// round 4
// speedup vs baseline: 2.0585x; 1.0811x over previous
#include <cuda_runtime.h>
#include <math.h>
#include <float.h>

// ---------------- problem constants ----------------
#define F_DIM 2048
#define H_DIM 256
#define C_DIM 64
#define K_DIM 16
#define TOPK  10
#define N_MAX 65536
#define EPS   1e-6f
#define R_TOT (TOPK + C_DIM)     // 74 embedding rows
#define PADW  257                // padded row width for k4 smem

// f-embedding chunking: 10 rows share W2 loads, 64 K-chunks of 32
#define KCHF  64
#define KCSZF (F_DIM / KCHF)     // 32
// proto-embedding chunking: 8 rows/group, 32 K-chunks of 64
#define RGP   8
#define KCHP  32
#define KCSZP (F_DIM / KCHP)     // 64

// ---------------- device scratch ----------------
__device__ float g_scores[N_MAX];
__device__ int   g_topidx[TOPK];
__device__ float g_part_f[TOPK * KCHF * H_DIM];
__device__ float g_part_p[C_DIM * KCHP * H_DIM];
__device__ float g_fp[R_TOT * H_DIM];   // rows 0..9 = f, 10..73 = p

// ---------------- K1: scores = x . (W3[:,1]-W3[:,0]) + (b3[1]-b3[0]) ----------------
// w_diff computed in-block from W3 (L2-hot). 16 rows per block, 1 row/warp.
__global__ void __launch_bounds__(512) k1_scores(const float* __restrict__ x,
                                                 const float* __restrict__ W3,
                                                 const float* __restrict__ b3,
                                                 int N) {
    __shared__ float ws[F_DIM];
    int tid = threadIdx.x;
    // each thread computes 4 w_diff entries from 2 float4s of W3
    const float4* w34 = reinterpret_cast<const float4*>(W3);   // 1024 float4
    float4 a = w34[2 * tid];
    float4 b = w34[2 * tid + 1];
    ws[4 * tid + 0] = a.y - a.x;
    ws[4 * tid + 1] = a.w - a.z;
    ws[4 * tid + 2] = b.y - b.x;
    ws[4 * tid + 3] = b.w - b.z;
    __syncthreads();

    int warp = tid >> 5;
    int lane = tid & 31;
    int row  = blockIdx.x * 16 + warp;
    if (row >= N) return;

    const float4* ws4 = reinterpret_cast<const float4*>(ws);
    const float4* xr  = reinterpret_cast<const float4*>(x + (size_t)row * F_DIM);
    float acc = 0.f;
#pragma unroll
    for (int it = 0; it < 16; it++) {
        float4 xv = __ldcs(&xr[lane + it * 32]);   // streaming: don't pollute L2
        float4 wv = ws4[lane + it * 32];
        acc = fmaf(xv.x, wv.x, acc);
        acc = fmaf(xv.y, wv.y, acc);
        acc = fmaf(xv.z, wv.z, acc);
        acc = fmaf(xv.w, wv.w, acc);
    }
#pragma unroll
    for (int o = 16; o; o >>= 1) acc += __shfl_down_sync(0xffffffffu, acc, o);
    if (lane == 0) g_scores[row] = acc + (b3[1] - b3[0]);
}

// ---------------- K2: top-10 selection ----------------
__device__ __forceinline__ bool better(float av, int ai, float bv, int bi) {
    return (av > bv) || (av == bv && ai < bi);
}

__global__ void __launch_bounds__(512) k2_topk(int N) {
    __shared__ float sv[512 * TOPK];
    __shared__ int   si[512 * TOPK];
    int tid = threadIdx.x;

    float lv[TOPK];
    int   li[TOPK];
#pragma unroll
    for (int j = 0; j < TOPK; j++) { lv[j] = -FLT_MAX; li[j] = 0x7fffffff; }

    const float4* s4 = reinterpret_cast<const float4*>(g_scores);
    int nv4 = N >> 2;
    for (int j0 = tid; j0 < nv4; j0 += 512 * 8) {
        float4 v[8];
        int    vi[8];
#pragma unroll
        for (int u = 0; u < 8; u++) {
            int j = j0 + 512 * u;
            vi[u] = j;
            if (j < nv4) v[u] = s4[j];
            else { v[u].x = v[u].y = v[u].z = v[u].w = -FLT_MAX; }
        }
#pragma unroll
        for (int u = 0; u < 8; u++) {
            float e[4] = { v[u].x, v[u].y, v[u].z, v[u].w };
#pragma unroll
            for (int q = 0; q < 4; q++) {
                int idx = vi[u] * 4 + q;
                if (better(e[q], idx, lv[TOPK - 1], li[TOPK - 1])) {
                    int j = TOPK - 1;
                    while (j > 0 && better(e[q], idx, lv[j - 1], li[j - 1])) {
                        lv[j] = lv[j - 1]; li[j] = li[j - 1]; j--;
                    }
                    lv[j] = e[q]; li[j] = idx;
                }
            }
        }
    }
#pragma unroll
    for (int j = 0; j < TOPK; j++) { sv[tid * TOPK + j] = lv[j]; si[tid * TOPK + j] = li[j]; }

    for (int s = 256; s > 0; s >>= 1) {
        __syncthreads();
        if (tid < s) {
            float mv[TOPK]; int mi[TOPK];
            int a = 0, b = 0;
#pragma unroll
            for (int j = 0; j < TOPK; j++) {
                float av = sv[tid * TOPK + a];        int ai = si[tid * TOPK + a];
                float bvv = sv[(tid + s) * TOPK + b]; int bi = si[(tid + s) * TOPK + b];
                if (better(av, ai, bvv, bi)) { mv[j] = av;  mi[j] = ai; a++; }
                else                         { mv[j] = bvv; mi[j] = bi; b++; }
            }
#pragma unroll
            for (int j = 0; j < TOPK; j++) { sv[tid * TOPK + j] = mv[j]; si[tid * TOPK + j] = mi[j]; }
        }
    }
    __syncthreads();
    if (tid < TOPK) g_topidx[tid] = si[tid];
}

// ---------------- K3 (f rows): 10 gathered rows @ W2, grid (1, KCHF) ----------------
__global__ void __launch_bounds__(256) k3a_f(const float* __restrict__ x,
                                             const float* __restrict__ W2) {
    __shared__ float xs[TOPK][KCSZF];
    int t  = threadIdx.x;
    int kc = blockIdx.y;
    int kbase = kc * KCSZF;

    for (int i = t; i < TOPK * KCSZF; i += 256) {
        int r = i / KCSZF, c = i % KCSZF;
        xs[r][c] = x[(size_t)g_topidx[r] * F_DIM + kbase + c];
    }
    __syncthreads();

    float acc[TOPK];
#pragma unroll
    for (int i = 0; i < TOPK; i++) acc[i] = 0.f;

#pragma unroll
    for (int k0 = 0; k0 < KCSZF; k0 += 8) {
        float w[8];
#pragma unroll
        for (int u = 0; u < 8; u++)
            w[u] = W2[(size_t)(kbase + k0 + u) * H_DIM + t];
#pragma unroll
        for (int u = 0; u < 8; u++)
#pragma unroll
            for (int i = 0; i < TOPK; i++)
                acc[i] = fmaf(xs[i][k0 + u], w[u], acc[i]);
    }

#pragma unroll
    for (int i = 0; i < TOPK; i++)
        g_part_f[((size_t)i * KCHF + kc) * H_DIM + t] = acc[i];
}

__global__ void __launch_bounds__(256) k3b_f(const float* __restrict__ b2) {
    int r = blockIdx.x;
    int t = threadIdx.x;
    float s = b2[t];
#pragma unroll 8
    for (int c = 0; c < KCHF; c++) s += g_part_f[((size_t)r * KCHF + c) * H_DIM + t];
    g_fp[r * H_DIM + t] = s;
}

// ---------------- K3 (proto rows): 64 rows @ W2, grid (8, KCHP) — SIDE STREAM ----------------
__global__ void __launch_bounds__(256) k3a_p(const float* __restrict__ proto,
                                             const float* __restrict__ W2) {
    __shared__ float xs[RGP][KCSZP];
    int t  = threadIdx.x;
    int rg = blockIdx.x;
    int kc = blockIdx.y;
    int kbase = kc * KCSZP;

    for (int i = t; i < RGP * KCSZP; i += 256) {
        int r = i >> 6, c = i & 63;   // KCSZP = 64
        xs[r][c] = proto[(size_t)(rg * RGP + r) * F_DIM + kbase + c];
    }
    __syncthreads();

    float acc[RGP];
#pragma unroll
    for (int i = 0; i < RGP; i++) acc[i] = 0.f;

    for (int k0 = 0; k0 < KCSZP; k0 += 8) {
        float w[8];
#pragma unroll
        for (int u = 0; u < 8; u++)
            w[u] = W2[(size_t)(kbase + k0 + u) * H_DIM + t];
#pragma unroll
        for (int u = 0; u < 8; u++)
#pragma unroll
            for (int i = 0; i < RGP; i++)
                acc[i] = fmaf(xs[i][k0 + u], w[u], acc[i]);
    }

#pragma unroll
    for (int i = 0; i < RGP; i++)
        g_part_p[((size_t)(rg * RGP + i) * KCHP + kc) * H_DIM + t] = acc[i];
}

__global__ void __launch_bounds__(256) k3b_p(const float* __restrict__ b2) {
    int r = blockIdx.x;                 // proto row 0..63
    int t = threadIdx.x;
    float s = b2[t];
#pragma unroll 8
    for (int c = 0; c < KCHP; c++) s += g_part_p[((size_t)r * KCHP + c) * H_DIM + t];
    g_fp[(TOPK + r) * H_DIM + t] = s;
}

// ---------------- K4: similarity + normalize + mean + head ----------------
__global__ void __launch_bounds__(640) k4_head(const float* __restrict__ Wrho,
                                               const float* __restrict__ brho,
                                               const float* __restrict__ Wc,
                                               const float* __restrict__ bc,
                                               float* __restrict__ out,
                                               int out_size) {
    extern __shared__ float rows[];          // R_TOT * PADW floats
    __shared__ float sim[TOPK][C_DIM];
    __shared__ float rowmax[TOPK];
    __shared__ float coding[C_DIM];
    __shared__ float hidden[K_DIM];
    __shared__ float logits[2];
    int t = threadIdx.x;

    for (int i = t; i < R_TOT * H_DIM; i += 640) {
        int r = i >> 8;
        int h = i & 255;
        float v = g_fp[i];
        if (r >= TOPK) v -= EPS;             // fold +EPS into prototype rows
        rows[r * PADW + h] = v;
    }
    __syncthreads();

    {
        int r = t / C_DIM;
        int c = t % C_DIM;
        const float* f = rows + r * PADW;
        const float* q = rows + (TOPK + c) * PADW;
        float s0 = 0.f, s1 = 0.f, s2 = 0.f, s3 = 0.f;
#pragma unroll 8
        for (int h = 0; h < H_DIM; h += 4) {
            float d0 = f[h]     - q[h];
            float d1 = f[h + 1] - q[h + 1];
            float d2 = f[h + 2] - q[h + 2];
            float d3 = f[h + 3] - q[h + 3];
            s0 = fmaf(d0, d0, s0);
            s1 = fmaf(d1, d1, s1);
            s2 = fmaf(d2, d2, s2);
            s3 = fmaf(d3, d3, s3);
        }
        sim[r][c] = sqrtf((s0 + s1) + (s2 + s3));
    }
    __syncthreads();
    if (t < TOPK) {
        float m = sim[t][0];
#pragma unroll
        for (int c = 1; c < C_DIM; c++) m = fmaxf(m, sim[t][c]);
        rowmax[t] = m;
    }
    __syncthreads();
    if (t < C_DIM) {
        float s = 0.f;
#pragma unroll
        for (int r = 0; r < TOPK; r++) s += sim[r][t] / rowmax[r];
        coding[t] = s / (float)TOPK;
    }
    __syncthreads();
    if (t < K_DIM) {
        float h = brho[t];
#pragma unroll
        for (int c = 0; c < C_DIM; c++) h = fmaf(coding[c], Wrho[c * K_DIM + t], h);
        hidden[t] = fmaxf(h, 0.f);
    }
    __syncthreads();
    if (t < 2) {
        float l = bc[t];
#pragma unroll
        for (int k = 0; k < K_DIM; k++) l = fmaf(hidden[k], Wc[k * 2 + t], l);
        logits[t] = l;
    }
    __syncthreads();
    if (t == 0) {
        float l0 = logits[0], l1 = logits[1];
        float m  = fmaxf(l0, l1);
        float e0 = expf(l0 - m), e1 = expf(l1 - m);
        float inv = 1.f / (e0 + e1);
        float p0 = e0 * inv, p1 = e1 * inv;

        float vals[5 + C_DIM];
        vals[0] = l0; vals[1] = l1;
        vals[2] = p0; vals[3] = p1;
        vals[4] = (p1 > p0) ? 1.f : 0.f;
#pragma unroll
        for (int c = 0; c < C_DIM; c++) vals[5 + c] = coding[c];

        int n = out_size < (5 + C_DIM) ? out_size : (5 + C_DIM);
        for (int i = 0; i < n; i++) out[i] = vals[i];
    }
}

// ---------------- host launcher ----------------
extern "C" void kernel_launch(void* const* d_in, const int* in_sizes, int n_in,
                              void* d_out, int out_size) {
    const float* x     = (const float*)d_in[0];
    const float* proto = (const float*)d_in[1];
    const float* W3    = (const float*)d_in[2];
    const float* b3    = (const float*)d_in[3];
    const float* W2    = (const float*)d_in[4];
    const float* b2    = (const float*)d_in[5];
    const float* Wrho  = (const float*)d_in[6];
    const float* brho  = (const float*)d_in[7];
    const float* Wc    = (const float*)d_in[8];
    const float* bc    = (const float*)d_in[9];
    float* out = (float*)d_out;

    int N = in_sizes[0] / F_DIM;
    if (N > N_MAX) N = N_MAX;

    static cudaStream_t s_side = nullptr;
    static cudaEvent_t  ev_fork = nullptr, ev_join = nullptr;
    static int k4_smem = R_TOT * PADW * (int)sizeof(float);   // ~76 KB
    if (s_side == nullptr) {
        cudaStreamCreateWithFlags(&s_side, cudaStreamNonBlocking);
        cudaEventCreateWithFlags(&ev_fork, cudaEventDisableTiming);
        cudaEventCreateWithFlags(&ev_join, cudaEventDisableTiming);
        cudaFuncSetAttribute(k4_head, cudaFuncAttributeMaxDynamicSharedMemorySize, k4_smem);
    }

    // fork: prototype embedding is independent of top-k -> run beside k1/k2
    cudaEventRecord(ev_fork, 0);
    cudaStreamWaitEvent(s_side, ev_fork, 0);

    dim3 gp(RGP, KCHP);
    k3a_p<<<gp, 256, 0, s_side>>>(proto, W2);
    k3b_p<<<C_DIM, 256, 0, s_side>>>(b2);
    cudaEventRecord(ev_join, s_side);

    // main critical path
    k1_scores<<<(N + 15) / 16, 512>>>(x, W3, b3, N);
    k2_topk<<<1, 512>>>(N);
    dim3 gf(1, KCHF);
    k3a_f<<<gf, 256>>>(x, W2);
    k3b_f<<<TOPK, 256>>>(b2);

    cudaStreamWaitEvent(0, ev_join, 0);
    k4_head<<<1, 640, k4_smem>>>(Wrho, brho, Wc, bc, out, out_size);
}

// round 6
// speedup vs baseline: 3.3415x; 1.6232x over previous
#include <cuda_runtime.h>
#include <math.h>
#include <float.h>

// ---------------- problem constants ----------------
#define F_DIM 2048
#define H_DIM 256
#define C_DIM 64
#define K_DIM 16
#define TOPK  10
#define N_MAX 65536
#define EPS   1e-6f
#define R_TOT (TOPK + C_DIM)     // 74 embedding rows
#define PADW  257                // padded row width for k4 smem

// top-k phase 1 geometry
#define TKB   512                          // threads per top-k block
#define NB1   ((N_MAX + TKB - 1) / TKB)    // 128 blocks max

// f-embedding chunking: 10 rows share W2 loads, 64 K-chunks of 32
#define KCHF  64
#define KCSZF (F_DIM / KCHF)     // 32
// proto-embedding chunking: 8 rows/group, 32 K-chunks of 64
#define RGP   8
#define KCHP  32
#define KCSZP (F_DIM / KCHP)     // 64

// ---------------- device scratch ----------------
__device__ float g_scores[N_MAX];
__device__ float g_candv[NB1 * TOPK];
__device__ int   g_candi[NB1 * TOPK];
__device__ int   g_topidx[TOPK];
__device__ float g_part_f[TOPK * KCHF * H_DIM];
__device__ float g_part_p[C_DIM * KCHP * H_DIM];
__device__ float g_fp[R_TOT * H_DIM];   // rows 0..9 = f, 10..73 = p

// ---------------- K1: scores = x . (W3[:,1]-W3[:,0]) + (b3[1]-b3[0]) ----------------
__global__ void __launch_bounds__(512) k1_scores(const float* __restrict__ x,
                                                 const float* __restrict__ W3,
                                                 const float* __restrict__ b3,
                                                 int N) {
    __shared__ float ws[F_DIM];
    int tid = threadIdx.x;
    const float4* w34 = reinterpret_cast<const float4*>(W3);   // 1024 float4
    float4 a = w34[2 * tid];
    float4 b = w34[2 * tid + 1];
    ws[4 * tid + 0] = a.y - a.x;
    ws[4 * tid + 1] = a.w - a.z;
    ws[4 * tid + 2] = b.y - b.x;
    ws[4 * tid + 3] = b.w - b.z;
    __syncthreads();

    int warp = tid >> 5;
    int lane = tid & 31;
    int row  = blockIdx.x * 16 + warp;
    if (row >= N) return;

    const float4* ws4 = reinterpret_cast<const float4*>(ws);
    const float4* xr  = reinterpret_cast<const float4*>(x + (size_t)row * F_DIM);
    float acc = 0.f;
#pragma unroll
    for (int it = 0; it < 16; it++) {
        float4 xv = __ldcs(&xr[lane + it * 32]);
        float4 wv = ws4[lane + it * 32];
        acc = fmaf(xv.x, wv.x, acc);
        acc = fmaf(xv.y, wv.y, acc);
        acc = fmaf(xv.z, wv.z, acc);
        acc = fmaf(xv.w, wv.w, acc);
    }
#pragma unroll
    for (int o = 16; o; o >>= 1) acc += __shfl_down_sync(0xffffffffu, acc, o);
    if (lane == 0) g_scores[row] = acc + (b3[1] - b3[0]);
}

// ---------------- top-k helpers ----------------
__device__ __forceinline__ bool better(float av, int ai, float bv, int bi) {
    return (av > bv) || (av == bv && ai < bi);
}

// shared-memory log-tree merge of per-thread sorted TOPK lists.
// sv/si hold TKB lists; on exit, list of thread 0 is the block top-10.
__device__ __forceinline__ void tree_merge(float* sv, int* si, int tid) {
    for (int s = TKB / 2; s > 0; s >>= 1) {
        __syncthreads();
        if (tid < s) {
            float mv[TOPK]; int mi[TOPK];
            int a = 0, b = 0;
#pragma unroll
            for (int j = 0; j < TOPK; j++) {
                float av = sv[tid * TOPK + a];        int ai = si[tid * TOPK + a];
                float bv = sv[(tid + s) * TOPK + b];  int bi = si[(tid + s) * TOPK + b];
                if (better(av, ai, bv, bi)) { mv[j] = av; mi[j] = ai; a++; }
                else                        { mv[j] = bv; mi[j] = bi; b++; }
            }
#pragma unroll
            for (int j = 0; j < TOPK; j++) { sv[tid * TOPK + j] = mv[j]; si[tid * TOPK + j] = mi[j]; }
        }
    }
    __syncthreads();
}

// ---------------- K2a: per-block top-10 (1 element per thread) ----------------
__global__ void __launch_bounds__(TKB) k2a_topk(int N) {
    __shared__ float sv[TKB * TOPK];
    __shared__ int   si[TKB * TOPK];
    int tid = threadIdx.x;
    int idx = blockIdx.x * TKB + tid;

    float v = (idx < N) ? g_scores[idx] : -FLT_MAX;
    // thread's sorted list: its single element then -inf padding
    sv[tid * TOPK] = v;  si[tid * TOPK] = idx;
#pragma unroll
    for (int j = 1; j < TOPK; j++) { sv[tid * TOPK + j] = -FLT_MAX; si[tid * TOPK + j] = 0x7fffffff; }

    tree_merge(sv, si, tid);

    if (tid < TOPK) {
        g_candv[blockIdx.x * TOPK + tid] = sv[tid];
        g_candi[blockIdx.x * TOPK + tid] = si[tid];
    }
}

// ---------------- K2b: merge candidates -> global top-10 ----------------
__global__ void __launch_bounds__(TKB) k2b_topk(int nb1) {
    __shared__ float sv[TKB * TOPK];
    __shared__ int   si[TKB * TOPK];
    int tid = threadIdx.x;
    int nc = nb1 * TOPK;

    float lv[TOPK]; int li[TOPK];
#pragma unroll
    for (int j = 0; j < TOPK; j++) { lv[j] = -FLT_MAX; li[j] = 0x7fffffff; }

    for (int i = tid; i < nc; i += TKB) {         // <=3 inserts per thread
        float v = g_candv[i];
        int   ix = g_candi[i];
        if (better(v, ix, lv[TOPK - 1], li[TOPK - 1])) {
            int j = TOPK - 1;
            while (j > 0 && better(v, ix, lv[j - 1], li[j - 1])) {
                lv[j] = lv[j - 1]; li[j] = li[j - 1]; j--;
            }
            lv[j] = v; li[j] = ix;
        }
    }
#pragma unroll
    for (int j = 0; j < TOPK; j++) { sv[tid * TOPK + j] = lv[j]; si[tid * TOPK + j] = li[j]; }

    tree_merge(sv, si, tid);

    if (tid < TOPK) g_topidx[tid] = si[tid];
}

// ---------------- K3 (f rows): 10 gathered rows @ W2, grid (1, KCHF) ----------------
__global__ void __launch_bounds__(256) k3a_f(const float* __restrict__ x,
                                             const float* __restrict__ W2) {
    __shared__ float xs[TOPK][KCSZF];
    int t  = threadIdx.x;
    int kc = blockIdx.y;
    int kbase = kc * KCSZF;

    for (int i = t; i < TOPK * KCSZF; i += 256) {
        int r = i / KCSZF, c = i % KCSZF;
        xs[r][c] = x[(size_t)g_topidx[r] * F_DIM + kbase + c];
    }
    __syncthreads();

    float acc[TOPK];
#pragma unroll
    for (int i = 0; i < TOPK; i++) acc[i] = 0.f;

#pragma unroll
    for (int k0 = 0; k0 < KCSZF; k0 += 8) {
        float w[8];
#pragma unroll
        for (int u = 0; u < 8; u++)
            w[u] = W2[(size_t)(kbase + k0 + u) * H_DIM + t];
#pragma unroll
        for (int u = 0; u < 8; u++)
#pragma unroll
            for (int i = 0; i < TOPK; i++)
                acc[i] = fmaf(xs[i][k0 + u], w[u], acc[i]);
    }

#pragma unroll
    for (int i = 0; i < TOPK; i++)
        g_part_f[((size_t)i * KCHF + kc) * H_DIM + t] = acc[i];
}

__global__ void __launch_bounds__(256) k3b_f(const float* __restrict__ b2) {
    int r = blockIdx.x;
    int t = threadIdx.x;
    float s = b2[t];
#pragma unroll 8
    for (int c = 0; c < KCHF; c++) s += g_part_f[((size_t)r * KCHF + c) * H_DIM + t];
    g_fp[r * H_DIM + t] = s;
}

// ---------------- K3 (proto rows): side stream ----------------
__global__ void __launch_bounds__(256) k3a_p(const float* __restrict__ proto,
                                             const float* __restrict__ W2) {
    __shared__ float xs[RGP][KCSZP];
    int t  = threadIdx.x;
    int rg = blockIdx.x;
    int kc = blockIdx.y;
    int kbase = kc * KCSZP;

    for (int i = t; i < RGP * KCSZP; i += 256) {
        int r = i >> 6, c = i & 63;
        xs[r][c] = proto[(size_t)(rg * RGP + r) * F_DIM + kbase + c];
    }
    __syncthreads();

    float acc[RGP];
#pragma unroll
    for (int i = 0; i < RGP; i++) acc[i] = 0.f;

    for (int k0 = 0; k0 < KCSZP; k0 += 8) {
        float w[8];
#pragma unroll
        for (int u = 0; u < 8; u++)
            w[u] = W2[(size_t)(kbase + k0 + u) * H_DIM + t];
#pragma unroll
        for (int u = 0; u < 8; u++)
#pragma unroll
            for (int i = 0; i < RGP; i++)
                acc[i] = fmaf(xs[i][k0 + u], w[u], acc[i]);
    }

#pragma unroll
    for (int i = 0; i < RGP; i++)
        g_part_p[((size_t)(rg * RGP + i) * KCHP + kc) * H_DIM + t] = acc[i];
}

__global__ void __launch_bounds__(256) k3b_p(const float* __restrict__ b2) {
    int r = blockIdx.x;
    int t = threadIdx.x;
    float s = b2[t];
#pragma unroll 8
    for (int c = 0; c < KCHP; c++) s += g_part_p[((size_t)r * KCHP + c) * H_DIM + t];
    g_fp[(TOPK + r) * H_DIM + t] = s;
}

// ---------------- K4: similarity + normalize + mean + head ----------------
__global__ void __launch_bounds__(640) k4_head(const float* __restrict__ Wrho,
                                               const float* __restrict__ brho,
                                               const float* __restrict__ Wc,
                                               const float* __restrict__ bc,
                                               float* __restrict__ out,
                                               int out_size) {
    extern __shared__ float rows[];          // R_TOT * PADW floats
    __shared__ float sim[TOPK][C_DIM];
    __shared__ float rowmax[TOPK];
    __shared__ float coding[C_DIM];
    __shared__ float hidden[K_DIM];
    __shared__ float logits[2];
    int t = threadIdx.x;

    for (int i = t; i < R_TOT * H_DIM; i += 640) {
        int r = i >> 8;
        int h = i & 255;
        float v = g_fp[i];
        if (r >= TOPK) v -= EPS;
        rows[r * PADW + h] = v;
    }
    __syncthreads();

    {
        int r = t / C_DIM;
        int c = t % C_DIM;
        const float* f = rows + r * PADW;
        const float* q = rows + (TOPK + c) * PADW;
        float s0 = 0.f, s1 = 0.f, s2 = 0.f, s3 = 0.f;
#pragma unroll 8
        for (int h = 0; h < H_DIM; h += 4) {
            float d0 = f[h]     - q[h];
            float d1 = f[h + 1] - q[h + 1];
            float d2 = f[h + 2] - q[h + 2];
            float d3 = f[h + 3] - q[h + 3];
            s0 = fmaf(d0, d0, s0);
            s1 = fmaf(d1, d1, s1);
            s2 = fmaf(d2, d2, s2);
            s3 = fmaf(d3, d3, s3);
        }
        sim[r][c] = sqrtf((s0 + s1) + (s2 + s3));
    }
    __syncthreads();
    if (t < TOPK) {
        float m = sim[t][0];
#pragma unroll
        for (int c = 1; c < C_DIM; c++) m = fmaxf(m, sim[t][c]);
        rowmax[t] = m;
    }
    __syncthreads();
    if (t < C_DIM) {
        float s = 0.f;
#pragma unroll
        for (int r = 0; r < TOPK; r++) s += sim[r][t] / rowmax[r];
        coding[t] = s / (float)TOPK;
    }
    __syncthreads();
    if (t < K_DIM) {
        float h = brho[t];
#pragma unroll
        for (int c = 0; c < C_DIM; c++) h = fmaf(coding[c], Wrho[c * K_DIM + t], h);
        hidden[t] = fmaxf(h, 0.f);
    }
    __syncthreads();
    if (t < 2) {
        float l = bc[t];
#pragma unroll
        for (int k = 0; k < K_DIM; k++) l = fmaf(hidden[k], Wc[k * 2 + t], l);
        logits[t] = l;
    }
    __syncthreads();
    if (t == 0) {
        float l0 = logits[0], l1 = logits[1];
        float m  = fmaxf(l0, l1);
        float e0 = expf(l0 - m), e1 = expf(l1 - m);
        float inv = 1.f / (e0 + e1);
        float p0 = e0 * inv, p1 = e1 * inv;

        float vals[5 + C_DIM];
        vals[0] = l0; vals[1] = l1;
        vals[2] = p0; vals[3] = p1;
        vals[4] = (p1 > p0) ? 1.f : 0.f;
#pragma unroll
        for (int c = 0; c < C_DIM; c++) vals[5 + c] = coding[c];

        int n = out_size < (5 + C_DIM) ? out_size : (5 + C_DIM);
        for (int i = 0; i < n; i++) out[i] = vals[i];
    }
}

// ---------------- host launcher ----------------
extern "C" void kernel_launch(void* const* d_in, const int* in_sizes, int n_in,
                              void* d_out, int out_size) {
    const float* x     = (const float*)d_in[0];
    const float* proto = (const float*)d_in[1];
    const float* W3    = (const float*)d_in[2];
    const float* b3    = (const float*)d_in[3];
    const float* W2    = (const float*)d_in[4];
    const float* b2    = (const float*)d_in[5];
    const float* Wrho  = (const float*)d_in[6];
    const float* brho  = (const float*)d_in[7];
    const float* Wc    = (const float*)d_in[8];
    const float* bc    = (const float*)d_in[9];
    float* out = (float*)d_out;

    int N = in_sizes[0] / F_DIM;
    if (N > N_MAX) N = N_MAX;
    int nb1 = (N + TKB - 1) / TKB;

    static cudaStream_t s_side = nullptr;
    static cudaEvent_t  ev_fork = nullptr, ev_join = nullptr;
    static int k4_smem = R_TOT * PADW * (int)sizeof(float);   // ~76 KB
    if (s_side == nullptr) {
        cudaStreamCreateWithFlags(&s_side, cudaStreamNonBlocking);
        cudaEventCreateWithFlags(&ev_fork, cudaEventDisableTiming);
        cudaEventCreateWithFlags(&ev_join, cudaEventDisableTiming);
        cudaFuncSetAttribute(k4_head, cudaFuncAttributeMaxDynamicSharedMemorySize, k4_smem);
    }

    // fork: prototype embedding independent of top-k
    cudaEventRecord(ev_fork, 0);
    cudaStreamWaitEvent(s_side, ev_fork, 0);

    dim3 gp(RGP, KCHP);
    k3a_p<<<gp, 256, 0, s_side>>>(proto, W2);
    k3b_p<<<C_DIM, 256, 0, s_side>>>(b2);
    cudaEventRecord(ev_join, s_side);

    // main critical path
    k1_scores<<<(N + 15) / 16, 512>>>(x, W3, b3, N);
    k2a_topk<<<nb1, TKB>>>(N);
    k2b_topk<<<1, TKB>>>(nb1);
    dim3 gf(1, KCHF);
    k3a_f<<<gf, 256>>>(x, W2);
    k3b_f<<<TOPK, 256>>>(b2);

    cudaStreamWaitEvent(0, ev_join, 0);
    k4_head<<<1, 640, k4_smem>>>(Wrho, brho, Wc, bc, out, out_size);
}